// round 11
// baseline (speedup 1.0000x reference)
#include <cuda_runtime.h>

#define NROWS  32768
#define DCOLS  2048
#define C4TOT  (DCOLS / 4)      // 512 float4 per row
#define NSTG   16               // column stages
#define SC4    32               // float4 cols per stage
#define SSC    (SC4 * 4)        // 128 scalar cols per stage
#define EPS    1e-6f

// Allocation-free scratch; every field returns to zero each launch.
__device__ __align__(16) float g_u[DCOLS];
__device__ __align__(16) float g_s[DCOLS];   // 0 = "not ready" sentinel
__device__ int   g_cnt[DCOLS];
__device__ int   g_done[NSTG];

// ---------------------------------------------------------------------------
// Cross-worker combine (32 workers -> 8 sacc rows -> sum) + per-column
// finalize via the proven arrival-counter + atomicExch pattern.
__device__ __forceinline__ void combine_finalize(
    float* sacc, int s, int tid, int c4l, int w, int nsm,
    float ax, float ay, float az, float aw)
{
    __syncthreads();                           // sacc free from previous use
    const int slot = w & 7;
#pragma unroll
    for (int rd = 0; rd < 4; ++rd) {
        if ((w >> 3) == rd) {
            float* p = &sacc[slot * SSC + c4l * 4];
            if (rd == 0) { p[0] = ax;  p[1] = ay;  p[2] = az;  p[3] = aw; }
            else         { p[0] += ax; p[1] += ay; p[2] += az; p[3] += aw; }
        }
        __syncthreads();
    }
    if (tid < SSC) {
        float v = 0.f;
#pragma unroll
        for (int k = 0; k < 8; ++k) v += sacc[k * SSC + tid];
        const int scol = s * SSC + tid;
        atomicAdd(&g_u[scol], v);
        __threadfence();                       // publish before counting
        if (atomicAdd(&g_cnt[scol], 1) == nsm - 1) {
            float tot = atomicExch(&g_u[scol], 0.f);          // sum + reset
            atomicExch(&g_s[scol], rsqrtf(tot + EPS));        // publish (!=0)
            g_cnt[scol] = 0;                                  // replay reset
        }
    }
}

// Spin until this stage's scales are published, then load own float4.
__device__ __forceinline__ float4 spin_get_scale(int s, int tid, int c4l)
{
    if (tid < SC4) {
        volatile float* gs = &g_s[s * SSC + tid * 4];
        while (gs[0] == 0.f || gs[1] == 0.f || gs[2] == 0.f || gs[3] == 0.f)
            __nanosleep(128);
    }
    __syncthreads();
    return __ldcg(reinterpret_cast<const float4*>(&g_s[s * SSC]) + c4l);
}

// Last-consumer reset of a stage's scales (replay-safe initial state).
__device__ __forceinline__ void consume_reset(int s, int tid, int nsm)
{
    if (tid == 0) {
        if (atomicAdd(&g_done[s], 1) == nsm - 1) {
            for (int k = 0; k < SSC; ++k)
                atomicExch(&g_s[s * SSC + k], 0.f);
            g_done[s] = 0;
        }
    }
}

// ---------------------------------------------------------------------------
// Persistent kernel. CTA bid owns rows [r0,r1) (~216). Per stage: reduce its
// tile into SMEM while (from stage 1 on) scaling the previous stage's tile
// out of SMEM — interleaved in the same instruction stream so the DRAM read
// and write directions run concurrently. x is read EXACTLY ONCE from DRAM.
__global__ void __launch_bounds__(1024, 1)
colnorm_persist(const float4* __restrict__ x, float4* __restrict__ y,
                int nsm, int maxr)
{
    extern __shared__ float4 smbuf[];          // [2][maxr][SC4] + sacc tail
    float* sacc = (float*)(smbuf + 2 * maxr * SC4);

    const int tid = threadIdx.x;
    const int c4l = tid & (SC4 - 1);           // 0..31 float4 col in stage
    const int w   = tid >> 5;                  // 0..31 row worker
    const int bid = blockIdx.x;
    const int r0  = (int)(((long long)bid * NROWS) / nsm);
    const int r1  = (int)(((long long)(bid + 1) * NROWS) / nsm);
    const int nr  = r1 - r0;

    const float4* xr = x + (size_t)r0 * C4TOT + c4l;
    float4*       yr = y + (size_t)r0 * C4TOT + c4l;

    float ax, ay, az, aw;

    // ---- stage 0: reduce only (fills buffer 0) ----
    {
        float4* bN = smbuf;
        ax = ay = az = aw = 0.f;
        int rl = w;
        for (; rl + 96 < nr; rl += 128) {
            float4 g0 = __ldcs(&xr[(size_t)(rl     ) * C4TOT]);
            float4 g1 = __ldcs(&xr[(size_t)(rl + 32) * C4TOT]);
            float4 g2 = __ldcs(&xr[(size_t)(rl + 64) * C4TOT]);
            float4 g3 = __ldcs(&xr[(size_t)(rl + 96) * C4TOT]);
            bN[(rl     ) * SC4 + c4l] = g0;
            bN[(rl + 32) * SC4 + c4l] = g1;
            bN[(rl + 64) * SC4 + c4l] = g2;
            bN[(rl + 96) * SC4 + c4l] = g3;
            ax = fmaf(g0.x, g0.x, ax); ay = fmaf(g0.y, g0.y, ay);
            az = fmaf(g0.z, g0.z, az); aw = fmaf(g0.w, g0.w, aw);
            ax = fmaf(g1.x, g1.x, ax); ay = fmaf(g1.y, g1.y, ay);
            az = fmaf(g1.z, g1.z, az); aw = fmaf(g1.w, g1.w, aw);
            ax = fmaf(g2.x, g2.x, ax); ay = fmaf(g2.y, g2.y, ay);
            az = fmaf(g2.z, g2.z, az); aw = fmaf(g2.w, g2.w, aw);
            ax = fmaf(g3.x, g3.x, ax); ay = fmaf(g3.y, g3.y, ay);
            az = fmaf(g3.z, g3.z, az); aw = fmaf(g3.w, g3.w, aw);
        }
        for (; rl < nr; rl += 32) {
            float4 g = __ldcs(&xr[(size_t)rl * C4TOT]);
            bN[rl * SC4 + c4l] = g;
            ax = fmaf(g.x, g.x, ax); ay = fmaf(g.y, g.y, ay);
            az = fmaf(g.z, g.z, az); aw = fmaf(g.w, g.w, aw);
        }
        combine_finalize(sacc, 0, tid, c4l, w, nsm, ax, ay, az, aw);
    }

    // ---- stages 1..NSTG-1: scale(s-1) from SMEM interleaved with reduce(s) ----
    for (int s = 1; s < NSTG; ++s) {
        const float4 s4 = spin_get_scale(s - 1, tid, c4l);
        float4* bO = smbuf + ((s - 1) & 1) * maxr * SC4;
        float4* bN = smbuf + ( s      & 1) * maxr * SC4;
        const size_t offN = (size_t)s * SC4;
        const size_t offO = (size_t)(s - 1) * SC4;

        ax = ay = az = aw = 0.f;
        int rl = w;
        for (; rl + 96 < nr; rl += 128) {
            // kick off next-stage global loads first (latency)
            float4 g0 = __ldcs(&xr[(size_t)(rl     ) * C4TOT + offN]);
            float4 g1 = __ldcs(&xr[(size_t)(rl + 32) * C4TOT + offN]);
            float4 g2 = __ldcs(&xr[(size_t)(rl + 64) * C4TOT + offN]);
            float4 g3 = __ldcs(&xr[(size_t)(rl + 96) * C4TOT + offN]);
            // scale previous stage from SMEM, stream to y
            float4 v0 = bO[(rl     ) * SC4 + c4l];
            float4 v1 = bO[(rl + 32) * SC4 + c4l];
            float4 v2 = bO[(rl + 64) * SC4 + c4l];
            float4 v3 = bO[(rl + 96) * SC4 + c4l];
            v0.x *= s4.x; v0.y *= s4.y; v0.z *= s4.z; v0.w *= s4.w;
            v1.x *= s4.x; v1.y *= s4.y; v1.z *= s4.z; v1.w *= s4.w;
            v2.x *= s4.x; v2.y *= s4.y; v2.z *= s4.z; v2.w *= s4.w;
            v3.x *= s4.x; v3.y *= s4.y; v3.z *= s4.z; v3.w *= s4.w;
            __stcs(&yr[(size_t)(rl     ) * C4TOT + offO], v0);
            __stcs(&yr[(size_t)(rl + 32) * C4TOT + offO], v1);
            __stcs(&yr[(size_t)(rl + 64) * C4TOT + offO], v2);
            __stcs(&yr[(size_t)(rl + 96) * C4TOT + offO], v3);
            // bank loaded values + accumulate squares
            bN[(rl     ) * SC4 + c4l] = g0;
            bN[(rl + 32) * SC4 + c4l] = g1;
            bN[(rl + 64) * SC4 + c4l] = g2;
            bN[(rl + 96) * SC4 + c4l] = g3;
            ax = fmaf(g0.x, g0.x, ax); ay = fmaf(g0.y, g0.y, ay);
            az = fmaf(g0.z, g0.z, az); aw = fmaf(g0.w, g0.w, aw);
            ax = fmaf(g1.x, g1.x, ax); ay = fmaf(g1.y, g1.y, ay);
            az = fmaf(g1.z, g1.z, az); aw = fmaf(g1.w, g1.w, aw);
            ax = fmaf(g2.x, g2.x, ax); ay = fmaf(g2.y, g2.y, ay);
            az = fmaf(g2.z, g2.z, az); aw = fmaf(g2.w, g2.w, aw);
            ax = fmaf(g3.x, g3.x, ax); ay = fmaf(g3.y, g3.y, ay);
            az = fmaf(g3.z, g3.z, az); aw = fmaf(g3.w, g3.w, aw);
        }
        for (; rl < nr; rl += 32) {
            float4 g = __ldcs(&xr[(size_t)rl * C4TOT + offN]);
            float4 v = bO[rl * SC4 + c4l];
            v.x *= s4.x; v.y *= s4.y; v.z *= s4.z; v.w *= s4.w;
            __stcs(&yr[(size_t)rl * C4TOT + offO], v);
            bN[rl * SC4 + c4l] = g;
            ax = fmaf(g.x, g.x, ax); ay = fmaf(g.y, g.y, ay);
            az = fmaf(g.z, g.z, az); aw = fmaf(g.w, g.w, aw);
        }
        consume_reset(s - 1, tid, nsm);
        combine_finalize(sacc, s, tid, c4l, w, nsm, ax, ay, az, aw);
    }

    // ---- epilogue: scale last stage from SMEM ----
    {
        const float4 s4 = spin_get_scale(NSTG - 1, tid, c4l);
        float4* bO = smbuf + ((NSTG - 1) & 1) * maxr * SC4;
        const size_t offO = (size_t)(NSTG - 1) * SC4;
        for (int rl = w; rl < nr; rl += 32) {
            float4 v = bO[rl * SC4 + c4l];
            v.x *= s4.x; v.y *= s4.y; v.z *= s4.z; v.w *= s4.w;
            __stcs(&yr[(size_t)rl * C4TOT + offO], v);
        }
        consume_reset(NSTG - 1, tid, nsm);
    }
}

// ---------------------------------------------------------------------------
extern "C" void kernel_launch(void* const* d_in, const int* in_sizes, int n_in,
                              void* d_out, int out_size) {
    const float4* x = (const float4*)d_in[0];
    float4*       y = (float4*)d_out;

    static int nsm = 0;
    static int maxr = 0;
    static size_t shbytes = 0;
    if (nsm == 0) {
        cudaDeviceProp prop;
        cudaGetDeviceProperties(&prop, 0);
        nsm  = prop.multiProcessorCount;                 // 152 on GB300
        maxr = (NROWS + nsm - 1) / nsm;                  // <=222 for nsm>=148
        shbytes = (size_t)2 * maxr * SC4 * sizeof(float4)  // double buffer
                + (size_t)8 * SSC * sizeof(float);         // sacc
        cudaFuncSetAttribute(colnorm_persist,
                             cudaFuncAttributeMaxDynamicSharedMemorySize,
                             (int)shbytes);
    }

    colnorm_persist<<<nsm, 1024, shbytes>>>(x, y, nsm, maxr);
}

// round 12
// speedup vs baseline: 1.4209x; 1.4209x over previous
#include <cuda_runtime.h>

#define NROWS   32768
#define DCOLS   2048
#define C4TOT   (DCOLS / 4)          // 512 float4 columns per row
#define GRPC4   128                  // float4 cols per column-group
#define NGRP    (C4TOT / GRPC4)      // 4 column-groups
#define GY      304                  // row-chunk blocks per group (2*152)
#define EPS     1e-6f

// Allocation-free scratch (__device__ globals); returned to zero by the
// kernels themselves so graph replays see identical initial state.
__device__ float g_u[DCOLS];         // column sum-of-squares accumulators
__device__ float g_s[DCOLS];         // rsqrt scales
__device__ int   g_cnt[DCOLS];       // per-column arrival counters

// ---------------------------------------------------------------------------
// Pass 1: column sum-of-squares over the WHOLE matrix in one launch.
// grid = (NGRP, GY), block = 512. blockIdx.x picks the 128-float4 column
// group; blockIdx.y the row chunk. Body identical to the R8 reduce that
// measured 6.4 TB/s. Finalize: proven arrival-counter + atomicExch pattern
// (GY contributors per column).
__global__ void __launch_bounds__(512)
reduceAll_kernel(const float4* __restrict__ x) {
    const int tid = threadIdx.x;
    const int c4l = tid & (GRPC4 - 1);               // 0..127
    const int w   = ((int)blockIdx.y << 2) + (tid >> 7); // row worker id
    const int W   = GY << 2;                         // 1216 row workers
    const size_t coff = (size_t)blockIdx.x * GRPC4 + c4l;

    float ax = 0.f, ay = 0.f, az = 0.f, aw = 0.f;
    int r = w;
    for (; r + 3 * W < NROWS; r += 4 * W) {
        float4 v0 = x[(size_t)(r        ) * C4TOT + coff];
        float4 v1 = x[(size_t)(r +     W) * C4TOT + coff];
        float4 v2 = x[(size_t)(r + 2 * W) * C4TOT + coff];
        float4 v3 = x[(size_t)(r + 3 * W) * C4TOT + coff];
        ax = fmaf(v0.x, v0.x, ax); ay = fmaf(v0.y, v0.y, ay);
        az = fmaf(v0.z, v0.z, az); aw = fmaf(v0.w, v0.w, aw);
        ax = fmaf(v1.x, v1.x, ax); ay = fmaf(v1.y, v1.y, ay);
        az = fmaf(v1.z, v1.z, az); aw = fmaf(v1.w, v1.w, aw);
        ax = fmaf(v2.x, v2.x, ax); ay = fmaf(v2.y, v2.y, ay);
        az = fmaf(v2.z, v2.z, az); aw = fmaf(v2.w, v2.w, aw);
        ax = fmaf(v3.x, v3.x, ax); ay = fmaf(v3.y, v3.y, ay);
        az = fmaf(v3.z, v3.z, az); aw = fmaf(v3.w, v3.w, aw);
    }
    for (; r < NROWS; r += W) {
        float4 v = x[(size_t)r * C4TOT + coff];
        ax = fmaf(v.x, v.x, ax); ay = fmaf(v.y, v.y, ay);
        az = fmaf(v.z, v.z, az); aw = fmaf(v.w, v.w, aw);
    }

    // Combine the 4 row-workers per column in shared (unique slots).
    __shared__ float sacc[4][GRPC4 * 4];
    const int rw = tid >> 7;
    sacc[rw][c4l * 4 + 0] = ax;
    sacc[rw][c4l * 4 + 1] = ay;
    sacc[rw][c4l * 4 + 2] = az;
    sacc[rw][c4l * 4 + 3] = aw;
    __syncthreads();

    // 512 threads -> the 512 scalar columns of this group
    const int scol = (int)blockIdx.x * (GRPC4 * 4) + tid;
    float v = sacc[0][tid] + sacc[1][tid] + sacc[2][tid] + sacc[3][tid];
    atomicAdd(&g_u[scol], v);
    __threadfence();                                 // publish before counting
    if (atomicAdd(&g_cnt[scol], 1) == GY - 1) {      // all GY blocks published
        float total = atomicExch(&g_u[scol], 0.0f);  // complete sum + reset
        g_s[scol]   = rsqrtf(total + EPS);
        g_cnt[scol] = 0;                             // reset for next replay
    }
}

// ---------------------------------------------------------------------------
// Pass 2: y = x * s[col] over the whole matrix, one launch. MLP=4: each
// thread owns one float4 position in 4 row-quarters; 4 independent ldcs
// batched before 4 stcs (best measured write rate, 3.39 TB/s). Write-capped,
// so read misses are bandwidth-free.
__global__ void __launch_bounds__(256)
scaleAll_kernel(const float4* __restrict__ x, float4* __restrict__ y) {
    const unsigned j   = blockIdx.x * 256u + threadIdx.x;  // 0..2^22-1
    const int      c4  = j & (C4TOT - 1);                  // 0..511
    const unsigned rq  = j >> 9;                           // row within quarter
    const size_t base  = (size_t)rq * C4TOT + c4;
    const size_t step  = (size_t)(NROWS / 4) * C4TOT;      // 8192-row stride

    const float4 s = ((const float4*)g_s)[c4];             // 8 KB, L1-hot

    float4 v0 = __ldcs(x + base);
    float4 v1 = __ldcs(x + base +     step);
    float4 v2 = __ldcs(x + base + 2 * step);
    float4 v3 = __ldcs(x + base + 3 * step);
    v0.x *= s.x; v0.y *= s.y; v0.z *= s.z; v0.w *= s.w;
    v1.x *= s.x; v1.y *= s.y; v1.z *= s.z; v1.w *= s.w;
    v2.x *= s.x; v2.y *= s.y; v2.z *= s.z; v2.w *= s.w;
    v3.x *= s.x; v3.y *= s.y; v3.z *= s.z; v3.w *= s.w;
    __stcs(y + base,            v0);
    __stcs(y + base +     step, v1);
    __stcs(y + base + 2 * step, v2);
    __stcs(y + base + 3 * step, v3);
}

// ---------------------------------------------------------------------------
extern "C" void kernel_launch(void* const* d_in, const int* in_sizes, int n_in,
                              void* d_out, int out_size) {
    const float4* x = (const float4*)d_in[0];
    float4*       y = (float4*)d_out;

    dim3 agrid(NGRP, GY);                           // (4, 304)
    reduceAll_kernel<<<agrid, 512>>>(x);

    // (NROWS/4)*C4TOT / 256 = 16384 blocks
    const unsigned bBlocks = (NROWS / 4) * C4TOT / 256;
    scaleAll_kernel<<<bBlocks, 256>>>(x, y);
}